// round 4
// baseline (speedup 1.0000x reference)
#include <cuda_runtime.h>
#include <math.h>

#define T_STEPS 4096
#define BATCH   32
#define DIN     256
#define HID     256
#define GATES   1024            // 4*HID
#define OUTD    512
#define CL_SZ   8               // CTAs per cluster
#define NBLK    128             // 16 clusters * 8

// ---------------- scratch (static device arrays are allowed) ---------------
__device__ float g_xz_f[(size_t)T_STEPS * BATCH * GATES];   // 512 MiB
__device__ float g_xz_b[(size_t)T_STEPS * BATCH * GATES];   // 512 MiB
__device__ float g_houts[(size_t)T_STEPS * BATCH * 2 * HID];// 256 MiB, [t][b][f|b]

__device__ __forceinline__ float sigf(float x)  { return 1.0f / (1.0f + __expf(-x)); }
__device__ __forceinline__ float tanhf_(float x){ return 1.0f - 2.0f / (__expf(2.0f * x) + 1.0f); }

__device__ __forceinline__ unsigned long long ffma2(
    unsigned long long a, unsigned long long b, unsigned long long c) {
    unsigned long long d;
    asm("fma.rn.f32x2 %0, %1, %2, %3;" : "=l"(d) : "l"(a), "l"(b), "l"(c));
    return d;
}

__device__ __forceinline__ unsigned smem_u32(const void* p) {
    return (unsigned)__cvta_generic_to_shared(p);
}

#define CLUSTER_SYNC() do { \
    asm volatile("barrier.cluster.arrive.aligned;" ::: "memory"); \
    asm volatile("barrier.cluster.wait.aligned;"   ::: "memory"); \
} while (0)

// ============================================================================
// GEMM 1: xz = x @ Wx + bias.  M=131072 (m=b*4096+t), N=1024, K=256.
// C row remapped to t*32+b (recurrence order). 128x128 tile, 8x8/thread.
// ============================================================================
__global__ void __launch_bounds__(256) k_gemm_xz(
    const float* __restrict__ A, const float* __restrict__ W,
    const float* __restrict__ bias, float* __restrict__ C)
{
    __shared__ float As[8][128];
    __shared__ float Bs[8][128];
    const int tid = threadIdx.x;
    const int n0 = blockIdx.x << 7;
    const int m0 = blockIdx.y << 7;
    const int am = tid >> 1, ak = (tid & 1) << 2;   // A loader
    const int bk = tid >> 5, bn = (tid & 31) << 2;  // B loader
    const int ty = tid >> 4, tx = tid & 15;
    float acc[8][8] = {};

    for (int k0 = 0; k0 < DIN; k0 += 8) {
        float4 av = *(const float4*)(A + (size_t)(m0 + am) * DIN + k0 + ak);
        float4 bv = *(const float4*)(W + (size_t)(k0 + bk) * GATES + n0 + bn);
        __syncthreads();
        As[ak + 0][am] = av.x; As[ak + 1][am] = av.y;
        As[ak + 2][am] = av.z; As[ak + 3][am] = av.w;
        *(float4*)&Bs[bk][bn] = bv;
        __syncthreads();
#pragma unroll
        for (int kk = 0; kk < 8; kk++) {
            float ar[8], br[8];
            *(float4*)&ar[0] = *(const float4*)&As[kk][(ty << 3) + 0];
            *(float4*)&ar[4] = *(const float4*)&As[kk][(ty << 3) + 4];
            *(float4*)&br[0] = *(const float4*)&Bs[kk][(tx << 3) + 0];
            *(float4*)&br[4] = *(const float4*)&Bs[kk][(tx << 3) + 4];
#pragma unroll
            for (int r = 0; r < 8; r++)
#pragma unroll
                for (int c = 0; c < 8; c++) acc[r][c] = fmaf(ar[r], br[c], acc[r][c]);
        }
    }
    float bi[8];
    *(float4*)&bi[0] = *(const float4*)(bias + n0 + (tx << 3) + 0);
    *(float4*)&bi[4] = *(const float4*)(bias + n0 + (tx << 3) + 4);
#pragma unroll
    for (int r = 0; r < 8; r++) {
        int m = m0 + (ty << 3) + r;
        int t = m & (T_STEPS - 1), b = m >> 12;
        float* dst = C + (size_t)(t * BATCH + b) * GATES + n0 + (tx << 3);
        float4 o0, o1;
        o0.x = acc[r][0] + bi[0]; o0.y = acc[r][1] + bi[1];
        o0.z = acc[r][2] + bi[2]; o0.w = acc[r][3] + bi[3];
        o1.x = acc[r][4] + bi[4]; o1.y = acc[r][5] + bi[5];
        o1.z = acc[r][6] + bi[6]; o1.w = acc[r][7] + bi[7];
        *(float4*)(dst + 0) = o0;
        *(float4*)(dst + 4) = o1;
    }
}

// ============================================================================
// GEMM 2: out = relu(h_cat) @ W_dense + b.  M=131072 (m=t*32+b), K=512, N=512.
// ============================================================================
__global__ void __launch_bounds__(256) k_gemm_dense(
    const float* __restrict__ W, const float* __restrict__ bias,
    float* __restrict__ out)
{
    __shared__ float As[8][128];
    __shared__ float Bs[8][128];
    const int tid = threadIdx.x;
    const int n0 = blockIdx.x << 7;
    const int m0 = blockIdx.y << 7;
    const int am = tid >> 1, ak = (tid & 1) << 2;
    const int bk = tid >> 5, bn = (tid & 31) << 2;
    const int ty = tid >> 4, tx = tid & 15;
    float acc[8][8] = {};

    for (int k0 = 0; k0 < 2 * HID; k0 += 8) {
        float4 av = *(const float4*)(g_houts + (size_t)(m0 + am) * (2 * HID) + k0 + ak);
        av.x = fmaxf(av.x, 0.f); av.y = fmaxf(av.y, 0.f);
        av.z = fmaxf(av.z, 0.f); av.w = fmaxf(av.w, 0.f);
        float4 bv = *(const float4*)(W + (size_t)(k0 + bk) * OUTD + n0 + bn);
        __syncthreads();
        As[ak + 0][am] = av.x; As[ak + 1][am] = av.y;
        As[ak + 2][am] = av.z; As[ak + 3][am] = av.w;
        *(float4*)&Bs[bk][bn] = bv;
        __syncthreads();
#pragma unroll
        for (int kk = 0; kk < 8; kk++) {
            float ar[8], br[8];
            *(float4*)&ar[0] = *(const float4*)&As[kk][(ty << 3) + 0];
            *(float4*)&ar[4] = *(const float4*)&As[kk][(ty << 3) + 4];
            *(float4*)&br[0] = *(const float4*)&Bs[kk][(tx << 3) + 0];
            *(float4*)&br[4] = *(const float4*)&Bs[kk][(tx << 3) + 4];
#pragma unroll
            for (int r = 0; r < 8; r++)
#pragma unroll
                for (int c = 0; c < 8; c++) acc[r][c] = fmaf(ar[r], br[c], acc[r][c]);
        }
    }
    float bi[8];
    *(float4*)&bi[0] = *(const float4*)(bias + n0 + (tx << 3) + 0);
    *(float4*)&bi[4] = *(const float4*)(bias + n0 + (tx << 3) + 4);
#pragma unroll
    for (int r = 0; r < 8; r++) {
        int m = m0 + (ty << 3) + r;
        int b = m & 31, t = m >> 5;
        float* dst = out + ((size_t)b * T_STEPS + t) * OUTD + n0 + (tx << 3);
        float4 o0, o1;
        o0.x = acc[r][0] + bi[0]; o0.y = acc[r][1] + bi[1];
        o0.z = acc[r][2] + bi[2]; o0.w = acc[r][3] + bi[3];
        o1.x = acc[r][4] + bi[4]; o1.y = acc[r][5] + bi[5];
        o1.z = acc[r][6] + bi[6]; o1.w = acc[r][7] + bi[7];
        *(float4*)(dst + 0) = o0;
        *(float4*)(dst + 4) = o1;
    }
}

// ============================================================================
// Recurrence: 16 clusters x 8 CTAs. Cluster c owns batches {2c, 2c+1}.
// CTA rank r owns h-cols [r*32, r*32+32) -> gate cols gate*256 + r*32 + jl.
// Weights register-resident (64 f32x2 pairs along k). Per step:
//   compute z partials (f32x2) -> smem reduce -> gates -> push new h to all
//   8 peers via st.shared::cluster -> cluster.sync. No global atomics.
// ============================================================================
__global__ void __cluster_dims__(CL_SZ, 1, 1) __launch_bounds__(256, 1) k_recur(
    const float* __restrict__ carry_c, const float* __restrict__ carry_h,
    const float* __restrict__ Wh_f, const float* __restrict__ Wh_b)
{
    __shared__ float h_s[2][2][HID];     // [buf][batch][k]  4 KB
    __shared__ float p_s[2 * 2 * 128];   // [kseg][batch][col] 2 KB
    __shared__ float z_s[2 * 128];       // [batch][col]

    const int tid  = threadIdx.x;
    const int rank = blockIdx.x & (CL_SZ - 1);
    const int b0   = (blockIdx.x >> 3) << 1;       // first batch (2 per cluster)
    const int jbase = rank << 5;                   // first h-col

    // compute mapping: 2 ksegs x 128 cols
    const int kseg = tid >> 7;
    const int col  = tid & 127;
    const int gate = col >> 5, jl = col & 31;
    const int gc   = (gate << 8) + jbase + jl;     // global gate col

    // z-combine mapping
    const int bz = tid >> 7, cz = tid & 127;
    const int gz = cz >> 5,  jz = cz & 31;

    // pointwise mapping (tid < 64)
    const int bp = tid >> 5, jp = tid & 31;

    // init h (each CTA keeps a full copy of its 2 batches' h)
    for (int i = tid; i < 2 * HID; i += 256)
        h_s[0][i >> 8][i & 255] = carry_h[(size_t)(b0 + (i >> 8)) * HID + (i & 255)];

    // cell state lives in pointwise threads' registers
    float c_reg = 0.f;
    unsigned rem_h[2][CL_SZ];     // peer smem addresses for both h buffers
    if (tid < 64) {
        c_reg = carry_c[(size_t)(b0 + bp) * HID + jbase + jp];
#pragma unroll
        for (int buf = 0; buf < 2; buf++) {
            unsigned loc = smem_u32(&h_s[buf][bp][jbase + jp]);
#pragma unroll
            for (int p = 0; p < CL_SZ; p++)
                asm("mapa.shared::cluster.u32 %0, %1, %2;"
                    : "=r"(rem_h[buf][p]) : "r"(loc), "r"(p));
        }
    }
    __syncthreads();

    int gs = 0;
    for (int dir = 0; dir < 2; dir++) {
        const float* __restrict__ Wh = dir ? Wh_b : Wh_f;
        const float* __restrict__ xz = dir ? g_xz_b : g_xz_f;
        const int half = dir ? HID : 0;

        // register-resident weight slice: pairs along k
        unsigned long long w2[64];
#pragma unroll
        for (int kk = 0; kk < 64; kk++) {
            float lo = Wh[(size_t)((kseg << 7) + 2 * kk + 0) * GATES + gc];
            float hi = Wh[(size_t)((kseg << 7) + 2 * kk + 1) * GATES + gc];
            union { float f[2]; unsigned long long u; } P;
            P.f[0] = lo; P.f[1] = hi;
            w2[kk] = P.u;
        }

        for (int s = 0; s < T_STEPS; s++, gs++) {
            const int t   = dir ? (T_STEPS - 1 - s) : s;
            const int cur = gs & 1, nxt = cur ^ 1;

            // xz for this thread's z element (issued early, consumed later)
            const float xzv = __ldcg(xz + ((size_t)t * BATCH + b0 + bz) * GATES
                                        + (gz << 8) + jbase + jz);

            // z partials over this thread's 128-k segment, both batches
            unsigned long long acc0 = 0ull, acc1 = 0ull;
            {
                const float4* h0 = (const float4*)&h_s[cur][0][kseg << 7];
                const float4* h1 = (const float4*)&h_s[cur][1][kseg << 7];
#pragma unroll
                for (int q = 0; q < 32; q++) {
                    union { float4 f; unsigned long long u[2]; } U0, U1;
                    U0.f = h0[q]; U1.f = h1[q];
                    acc0 = ffma2(U0.u[0], w2[2 * q + 0], acc0);
                    acc0 = ffma2(U0.u[1], w2[2 * q + 1], acc0);
                    acc1 = ffma2(U1.u[0], w2[2 * q + 0], acc1);
                    acc1 = ffma2(U1.u[1], w2[2 * q + 1], acc1);
                }
            }
            {
                union { unsigned long long u; float f[2]; } A0, A1;
                A0.u = acc0; A1.u = acc1;
                p_s[(kseg << 8) + (0 << 7) + col] = A0.f[0] + A0.f[1];
                p_s[(kseg << 8) + (1 << 7) + col] = A1.f[0] + A1.f[1];
            }
            __syncthreads();

            // z = xz + partial(kseg0) + partial(kseg1)
            z_s[(bz << 7) + cz] = xzv + p_s[(0 << 8) + (bz << 7) + cz]
                                      + p_s[(1 << 8) + (bz << 7) + cz];
            __syncthreads();

            // gates + state update + h broadcast to all cluster CTAs
            if (tid < 64) {
                const float zi = z_s[(bp << 7) +  0 + jp];
                const float zf = z_s[(bp << 7) + 32 + jp];
                const float zg = z_s[(bp << 7) + 64 + jp];
                const float zo = z_s[(bp << 7) + 96 + jp];
                c_reg = fmaf(sigf(zf), c_reg, sigf(zi) * tanhf_(zg));
                const float h = sigf(zo) * tanhf_(c_reg);
#pragma unroll
                for (int p = 0; p < CL_SZ; p++)
                    asm volatile("st.shared::cluster.f32 [%0], %1;"
                                 :: "r"(rem_h[nxt][p]), "f"(h) : "memory");
                g_houts[((size_t)t * BATCH + b0 + bp) * (2 * HID) + half + jbase + jp] = h;
            }
            CLUSTER_SYNC();   // publishes remote h stores; guards buffer reuse
        }
    }
}

// ---------------- launch ----------------------------------------------------
extern "C" void kernel_launch(void* const* d_in, const int* in_sizes, int n_in,
                              void* d_out, int out_size) {
    const float* carry_c = (const float*)d_in[0];
    const float* carry_h = (const float*)d_in[1];
    const float* x       = (const float*)d_in[2];
    const float* Wx_f    = (const float*)d_in[3];
    const float* Wh_f    = (const float*)d_in[4];
    const float* b_f     = (const float*)d_in[5];
    const float* Wx_b    = (const float*)d_in[6];
    const float* Wh_b    = (const float*)d_in[7];
    const float* b_b     = (const float*)d_in[8];
    const float* W_dense = (const float*)d_in[9];
    const float* b_dense = (const float*)d_in[10];
    float* out = (float*)d_out;

    float* xz_f; cudaGetSymbolAddress((void**)&xz_f, g_xz_f);
    float* xz_b; cudaGetSymbolAddress((void**)&xz_b, g_xz_b);

    dim3 g1(GATES / 128, (BATCH * T_STEPS) / 128);   // (8, 1024)
    k_gemm_xz<<<g1, 256>>>(x, Wx_f, b_f, xz_f);
    k_gemm_xz<<<g1, 256>>>(x, Wx_b, b_b, xz_b);

    k_recur<<<NBLK, 256>>>(carry_c, carry_h, Wh_f, Wh_b);

    dim3 g2(OUTD / 128, (BATCH * T_STEPS) / 128);    // (4, 1024)
    k_gemm_dense<<<g2, 256>>>(W_dense, b_dense, out);
}

// round 5
// speedup vs baseline: 1.0069x; 1.0069x over previous
#include <cuda_runtime.h>
#include <math.h>

#define T_STEPS 4096
#define BATCH   32
#define DIN     256
#define HID     256
#define GATES   1024            // 4*HID
#define OUTD    512
#define CL_SZ   8               // CTAs per cluster
#define NBLK    128             // 16 clusters * 8

// ---------------- scratch (static device arrays are allowed) ---------------
__device__ float g_xz_f[(size_t)T_STEPS * BATCH * GATES];   // 512 MiB
__device__ float g_xz_b[(size_t)T_STEPS * BATCH * GATES];   // 512 MiB
__device__ float g_houts[(size_t)T_STEPS * BATCH * 2 * HID];// 256 MiB, [t][b][f|b]

__device__ __forceinline__ float sigf(float x)  { return 1.0f / (1.0f + __expf(-x)); }
__device__ __forceinline__ float tanhf_(float x){ return 1.0f - 2.0f / (__expf(2.0f * x) + 1.0f); }

__device__ __forceinline__ unsigned long long ffma2(
    unsigned long long a, unsigned long long b, unsigned long long c) {
    unsigned long long d;
    asm("fma.rn.f32x2 %0, %1, %2, %3;" : "=l"(d) : "l"(a), "l"(b), "l"(c));
    return d;
}
__device__ __forceinline__ unsigned long long bcast2(float a) {
    unsigned long long d;
    asm("mov.b64 %0, {%1, %1};" : "=l"(d) : "f"(a));
    return d;
}
__device__ __forceinline__ unsigned smem_u32(const void* p) {
    return (unsigned)__cvta_generic_to_shared(p);
}

#define CLUSTER_SYNC() do { \
    asm volatile("barrier.cluster.arrive.aligned;" ::: "memory"); \
    asm volatile("barrier.cluster.wait.aligned;"   ::: "memory"); \
} while (0)

// ============================================================================
// GEMM 1: xz = x @ Wx + bias.  M=131072 (m=b*4096+t), N=1024, K=256.
// C row remapped to t*32+b. 128x128 tile, 8x8/thread, f32x2 packed FMA.
// ============================================================================
__global__ void __launch_bounds__(256) k_gemm_xz(
    const float* __restrict__ A, const float* __restrict__ W,
    const float* __restrict__ bias, float* __restrict__ C)
{
    __shared__ float As[8][128];
    __shared__ float Bs[8][128];
    const int tid = threadIdx.x;
    const int n0 = blockIdx.x << 7;
    const int m0 = blockIdx.y << 7;
    const int am = tid >> 1, ak = (tid & 1) << 2;   // A loader
    const int bk = tid >> 5, bn = (tid & 31) << 2;  // B loader
    const int ty = tid >> 4, tx = tid & 15;
    unsigned long long acc2[8][4] = {};

    for (int k0 = 0; k0 < DIN; k0 += 8) {
        float4 av = *(const float4*)(A + (size_t)(m0 + am) * DIN + k0 + ak);
        float4 bv = *(const float4*)(W + (size_t)(k0 + bk) * GATES + n0 + bn);
        __syncthreads();
        As[ak + 0][am] = av.x; As[ak + 1][am] = av.y;
        As[ak + 2][am] = av.z; As[ak + 3][am] = av.w;
        *(float4*)&Bs[bk][bn] = bv;
        __syncthreads();
#pragma unroll
        for (int kk = 0; kk < 8; kk++) {
            float ar[8];
            *(float4*)&ar[0] = *(const float4*)&As[kk][(ty << 3) + 0];
            *(float4*)&ar[4] = *(const float4*)&As[kk][(ty << 3) + 4];
            union { float4 f; unsigned long long u[2]; } B0, B1;
            B0.f = *(const float4*)&Bs[kk][(tx << 3) + 0];
            B1.f = *(const float4*)&Bs[kk][(tx << 3) + 4];
#pragma unroll
            for (int r = 0; r < 8; r++) {
                unsigned long long a2 = bcast2(ar[r]);
                acc2[r][0] = ffma2(a2, B0.u[0], acc2[r][0]);
                acc2[r][1] = ffma2(a2, B0.u[1], acc2[r][1]);
                acc2[r][2] = ffma2(a2, B1.u[0], acc2[r][2]);
                acc2[r][3] = ffma2(a2, B1.u[1], acc2[r][3]);
            }
        }
    }
    float bi[8];
    *(float4*)&bi[0] = *(const float4*)(bias + n0 + (tx << 3) + 0);
    *(float4*)&bi[4] = *(const float4*)(bias + n0 + (tx << 3) + 4);
#pragma unroll
    for (int r = 0; r < 8; r++) {
        int m = m0 + (ty << 3) + r;
        int t = m & (T_STEPS - 1), b = m >> 12;
        float* dst = C + (size_t)(t * BATCH + b) * GATES + n0 + (tx << 3);
        union { unsigned long long u; float f[2]; } U;
        float o[8];
#pragma unroll
        for (int c4 = 0; c4 < 4; c4++) {
            U.u = acc2[r][c4];
            o[2 * c4 + 0] = U.f[0] + bi[2 * c4 + 0];
            o[2 * c4 + 1] = U.f[1] + bi[2 * c4 + 1];
        }
        *(float4*)(dst + 0) = *(float4*)&o[0];
        *(float4*)(dst + 4) = *(float4*)&o[4];
    }
}

// ============================================================================
// GEMM 2: out = relu(h_cat) @ W_dense + b.  M=131072 (m=t*32+b), K=512, N=512.
// ============================================================================
__global__ void __launch_bounds__(256) k_gemm_dense(
    const float* __restrict__ W, const float* __restrict__ bias,
    float* __restrict__ out)
{
    __shared__ float As[8][128];
    __shared__ float Bs[8][128];
    const int tid = threadIdx.x;
    const int n0 = blockIdx.x << 7;
    const int m0 = blockIdx.y << 7;
    const int am = tid >> 1, ak = (tid & 1) << 2;
    const int bk = tid >> 5, bn = (tid & 31) << 2;
    const int ty = tid >> 4, tx = tid & 15;
    unsigned long long acc2[8][4] = {};

    for (int k0 = 0; k0 < 2 * HID; k0 += 8) {
        float4 av = *(const float4*)(g_houts + (size_t)(m0 + am) * (2 * HID) + k0 + ak);
        av.x = fmaxf(av.x, 0.f); av.y = fmaxf(av.y, 0.f);
        av.z = fmaxf(av.z, 0.f); av.w = fmaxf(av.w, 0.f);
        float4 bv = *(const float4*)(W + (size_t)(k0 + bk) * OUTD + n0 + bn);
        __syncthreads();
        As[ak + 0][am] = av.x; As[ak + 1][am] = av.y;
        As[ak + 2][am] = av.z; As[ak + 3][am] = av.w;
        *(float4*)&Bs[bk][bn] = bv;
        __syncthreads();
#pragma unroll
        for (int kk = 0; kk < 8; kk++) {
            float ar[8];
            *(float4*)&ar[0] = *(const float4*)&As[kk][(ty << 3) + 0];
            *(float4*)&ar[4] = *(const float4*)&As[kk][(ty << 3) + 4];
            union { float4 f; unsigned long long u[2]; } B0, B1;
            B0.f = *(const float4*)&Bs[kk][(tx << 3) + 0];
            B1.f = *(const float4*)&Bs[kk][(tx << 3) + 4];
#pragma unroll
            for (int r = 0; r < 8; r++) {
                unsigned long long a2 = bcast2(ar[r]);
                acc2[r][0] = ffma2(a2, B0.u[0], acc2[r][0]);
                acc2[r][1] = ffma2(a2, B0.u[1], acc2[r][1]);
                acc2[r][2] = ffma2(a2, B1.u[0], acc2[r][2]);
                acc2[r][3] = ffma2(a2, B1.u[1], acc2[r][3]);
            }
        }
    }
    float bi[8];
    *(float4*)&bi[0] = *(const float4*)(bias + n0 + (tx << 3) + 0);
    *(float4*)&bi[4] = *(const float4*)(bias + n0 + (tx << 3) + 4);
#pragma unroll
    for (int r = 0; r < 8; r++) {
        int m = m0 + (ty << 3) + r;
        int b = m & 31, t = m >> 5;
        float* dst = out + ((size_t)b * T_STEPS + t) * OUTD + n0 + (tx << 3);
        union { unsigned long long u; float f[2]; } U;
        float o[8];
#pragma unroll
        for (int c4 = 0; c4 < 4; c4++) {
            U.u = acc2[r][c4];
            o[2 * c4 + 0] = U.f[0] + bi[2 * c4 + 0];
            o[2 * c4 + 1] = U.f[1] + bi[2 * c4 + 1];
        }
        *(float4*)(dst + 0) = *(float4*)&o[0];
        *(float4*)(dst + 4) = *(float4*)&o[4];
    }
}

// ============================================================================
// Recurrence: 16 clusters x 8 CTAs, 512 threads/CTA. Cluster owns 2 batches;
// CTA rank r owns h-cols [r*32, r*32+32). Thread (kseg 0..3, col 0..127)
// holds 32 f32x2 weight regs (64 k-values x 1 gate-col) -> NO spill.
// Per step: partials -> __syncthreads -> 64 pointwise threads combine
// (prefetched xz regs + 8 partials), gate math, DSMEM-push new h to all
// 8 peers, prefetch next xz -> cluster.sync.
// ============================================================================
__global__ void __cluster_dims__(CL_SZ, 1, 1) __launch_bounds__(512, 1) k_recur(
    const float* __restrict__ carry_c, const float* __restrict__ carry_h,
    const float* __restrict__ Wh_f, const float* __restrict__ Wh_b)
{
    __shared__ float h_s[2][2][HID];     // [buf][batch][k]  4 KB
    __shared__ float p_s[4][2][128];     // [kseg][batch][col] 4 KB

    const int tid   = threadIdx.x;
    const int rank  = blockIdx.x & (CL_SZ - 1);
    const int b0    = (blockIdx.x >> 3) << 1;      // first batch
    const int jbase = rank << 5;                   // first h-col

    const int kseg = tid >> 7;                     // 0..3 (64 k each)
    const int col  = tid & 127;                    // 0..127
    const int gate = col >> 5, jl = col & 31;
    const int gc   = (gate << 8) + jbase + jl;     // global gate col

    const int bp = tid >> 5, jp = tid & 31;        // pointwise map (tid<64)

    // init h (full copy of this cluster's 2 batches)
    h_s[0][tid >> 8][tid & 255] =
        carry_h[(size_t)(b0 + (tid >> 8)) * HID + (tid & 255)];

    float c_reg = 0.f;
    unsigned rem_h[2][CL_SZ];
    if (tid < 64) {
        c_reg = carry_c[(size_t)(b0 + bp) * HID + jbase + jp];
#pragma unroll
        for (int buf = 0; buf < 2; buf++) {
            unsigned loc = smem_u32(&h_s[buf][bp][jbase + jp]);
#pragma unroll
            for (int p = 0; p < CL_SZ; p++)
                asm("mapa.shared::cluster.u32 %0, %1, %2;"
                    : "=r"(rem_h[buf][p]) : "r"(loc), "r"(p));
        }
    }
    __syncthreads();

    int gs = 0;
    for (int dir = 0; dir < 2; dir++) {
        const float* __restrict__ Wh = dir ? Wh_b : Wh_f;
        const float* __restrict__ xz = dir ? g_xz_b : g_xz_f;
        const int half = dir ? HID : 0;

        // register-resident weights: 64 k-values as 32 f32x2
        unsigned long long w2[32];
#pragma unroll
        for (int kk = 0; kk < 32; kk++) {
            union { float f[2]; unsigned long long u; } P;
            P.f[0] = Wh[(size_t)((kseg << 6) + 2 * kk + 0) * GATES + gc];
            P.f[1] = Wh[(size_t)((kseg << 6) + 2 * kk + 1) * GATES + gc];
            w2[kk] = P.u;
        }

        // prefetch xz for first step of this direction (pointwise threads)
        float xzp[4];
        if (tid < 64) {
            const int t0 = dir ? (T_STEPS - 1) : 0;
#pragma unroll
            for (int g = 0; g < 4; g++)
                xzp[g] = __ldcg(xz + ((size_t)t0 * BATCH + b0 + bp) * GATES
                                   + (g << 8) + jbase + jp);
        }

        for (int s = 0; s < T_STEPS; s++, gs++) {
            const int t   = dir ? (T_STEPS - 1 - s) : s;
            const int cur = gs & 1, nxt = cur ^ 1;

            // partial dot products over this thread's 64-k segment, 2 batches
            unsigned long long a0 = 0ull, a1 = 0ull;
            {
                const float4* h0 = (const float4*)&h_s[cur][0][kseg << 6];
                const float4* h1 = (const float4*)&h_s[cur][1][kseg << 6];
#pragma unroll
                for (int q = 0; q < 16; q++) {
                    union { float4 f; unsigned long long u[2]; } U0, U1;
                    U0.f = h0[q]; U1.f = h1[q];
                    a0 = ffma2(U0.u[0], w2[2 * q + 0], a0);
                    a0 = ffma2(U0.u[1], w2[2 * q + 1], a0);
                    a1 = ffma2(U1.u[0], w2[2 * q + 0], a1);
                    a1 = ffma2(U1.u[1], w2[2 * q + 1], a1);
                }
            }
            {
                union { unsigned long long u; float f[2]; } A0, A1;
                A0.u = a0; A1.u = a1;
                p_s[kseg][0][col] = A0.f[0] + A0.f[1];
                p_s[kseg][1][col] = A1.f[0] + A1.f[1];
            }
            __syncthreads();

            if (tid < 64) {
                float z[4];
#pragma unroll
                for (int g = 0; g < 4; g++) {
                    const int cc = (g << 5) + jp;
                    z[g] = xzp[g] + p_s[0][bp][cc] + p_s[1][bp][cc]
                                  + p_s[2][bp][cc] + p_s[3][bp][cc];
                }
                c_reg = fmaf(sigf(z[1]), c_reg, sigf(z[0]) * tanhf_(z[2]));
                const float h = sigf(z[3]) * tanhf_(c_reg);
#pragma unroll
                for (int p = 0; p < CL_SZ; p++)
                    asm volatile("st.shared::cluster.f32 [%0], %1;"
                                 :: "r"(rem_h[nxt][p]), "f"(h) : "memory");
                g_houts[((size_t)t * BATCH + b0 + bp) * (2 * HID)
                        + half + jbase + jp] = h;
                // prefetch next step's xz (hidden behind cluster.sync+compute)
                if (s + 1 < T_STEPS) {
                    const int tn = dir ? (T_STEPS - 2 - s) : (s + 1);
#pragma unroll
                    for (int g = 0; g < 4; g++)
                        xzp[g] = __ldcg(xz + ((size_t)tn * BATCH + b0 + bp) * GATES
                                           + (g << 8) + jbase + jp);
                }
            }
            CLUSTER_SYNC();   // publishes peer h stores; guards buffer reuse
        }
    }
}

// ---------------- launch ----------------------------------------------------
extern "C" void kernel_launch(void* const* d_in, const int* in_sizes, int n_in,
                              void* d_out, int out_size) {
    const float* carry_c = (const float*)d_in[0];
    const float* carry_h = (const float*)d_in[1];
    const float* x       = (const float*)d_in[2];
    const float* Wx_f    = (const float*)d_in[3];
    const float* Wh_f    = (const float*)d_in[4];
    const float* b_f     = (const float*)d_in[5];
    const float* Wx_b    = (const float*)d_in[6];
    const float* Wh_b    = (const float*)d_in[7];
    const float* b_b     = (const float*)d_in[8];
    const float* W_dense = (const float*)d_in[9];
    const float* b_dense = (const float*)d_in[10];
    float* out = (float*)d_out;

    float* xz_f; cudaGetSymbolAddress((void**)&xz_f, g_xz_f);
    float* xz_b; cudaGetSymbolAddress((void**)&xz_b, g_xz_b);

    dim3 g1(GATES / 128, (BATCH * T_STEPS) / 128);   // (8, 1024)
    k_gemm_xz<<<g1, 256>>>(x, Wx_f, b_f, xz_f);
    k_gemm_xz<<<g1, 256>>>(x, Wx_b, b_b, xz_b);

    k_recur<<<NBLK, 512>>>(carry_c, carry_h, Wh_f, Wh_b);

    dim3 g2(OUTD / 128, (BATCH * T_STEPS) / 128);    // (4, 1024)
    k_gemm_dense<<<g2, 256>>>(W_dense, b_dense, out);
}